// round 4
// baseline (speedup 1.0000x reference)
#include <cuda_runtime.h>
#include <math.h>

#define NPTS 16384
#define DIM  64
#define NC   9
#define TILE 64
#define NF4  16      // float4s per feature row
#define PITCHF4 17   // smem tile pitch in float4
#define NB3  512     // k3 grid

// ---- device scratch ----
__device__ float g_fn[NPTS * DIM];       // normalized features (valid points only)
__device__ float g_cf[NPTS * DIM];       // compacted class-sorted features (padded)
__device__ int   g_cls[NPTS];            // class 1..8 if valid member, else 0
__device__ int   g_cidx[NPTS];           // class-sorted point indices
__device__ int   g_ccls[NPTS];           // class-sorted classes (padded with 0)
__device__ int   g_nvalid;
__device__ int   g_cnt[NC];
__device__ float g_sum[NC * DIM];        // per-class normalized-feature sums
__device__ float g_cross[NC * NC];       // relu(dot) sums per unordered class pair
__device__ unsigned g_ticket;

// ---------------- K0: zero accumulators ----------------
__global__ void k0_zero() {
    int t = threadIdx.x;
    if (t < NC) g_cnt[t] = 0;
    if (t < NC * NC) g_cross[t] = 0.f;
    for (int i = t; i < NC * DIM; i += blockDim.x) g_sum[i] = 0.f;
    if (t == 0) { g_nvalid = 0; g_ticket = 0; }
}

// ---------------- K1: classify + normalize (1 warp / point) ----------------
__global__ void k1_classify(const int* __restrict__ labels,
                            const float* __restrict__ feats,
                            const float* __restrict__ scores) {
    int warp = (blockIdx.x * blockDim.x + threadIdx.x) >> 5;
    int lane = threadIdx.x & 31;
    if (warp >= NPTS) return;
    int p = warp;

    float x0 = feats[p * DIM + lane];
    float x1 = feats[p * DIM + 32 + lane];
    float ss = x0 * x0 + x1 * x1;
    #pragma unroll
    for (int o = 16; o > 0; o >>= 1) ss += __shfl_xor_sync(0xffffffffu, ss, o);
    float inv = 1.0f / fmaxf(sqrtf(ss), 1e-12f);

    float s = (lane < NC) ? scores[p * NC + lane] : -INFINITY;
    float mval = s; int midx = lane;
    #pragma unroll
    for (int o = 16; o > 0; o >>= 1) {
        float ov = __shfl_xor_sync(0xffffffffu, mval, o);
        int   oi = __shfl_xor_sync(0xffffffffu, midx, o);
        if (ov > mval || (ov == mval && oi < midx)) { mval = ov; midx = oi; }
    }
    float e = (lane < NC) ? expf(s - mval) : 0.f;
    #pragma unroll
    for (int o = 16; o > 0; o >>= 1) e += __shfl_xor_sync(0xffffffffu, e, o);
    float pmax = 1.0f / e;

    int lab = labels[p];
    int valid = (lab == midx) && (pmax >= 0.5f);
    int cls = (valid && lab >= 1) ? lab : 0;

    if (lane == 0) g_cls[p] = cls;
    if (cls > 0) {
        float f0 = x0 * inv, f1 = x1 * inv;
        g_fn[p * DIM + lane]      = f0;
        g_fn[p * DIM + 32 + lane] = f1;
        atomicAdd(&g_sum[cls * DIM + lane],      f0);
        atomicAdd(&g_sum[cls * DIM + 32 + lane], f1);
        if (lane == 0) atomicAdd(&g_cnt[cls], 1);
    }
}

// ------- K2: class-stable counting sort + compaction copy (1 block) --------
__global__ void k2_sort() {
    __shared__ int cstart[NC];
    __shared__ int running[NC];
    __shared__ int wcnt[NC][32];
    __shared__ int woff[NC][32];
    __shared__ int wtot[NC];
    int tid = threadIdx.x, lane = tid & 31, wid = tid >> 5;

    if (tid == 0) {
        int acc = 0;
        for (int c = 1; c < NC; c++) { cstart[c] = acc; acc += g_cnt[c]; }
        g_nvalid = acc;
    }
    if (tid < NC) running[tid] = 0;
    __syncthreads();

    unsigned lmask = (1u << lane) - 1u;
    for (int start = 0; start < NPTS; start += 1024) {
        int p = start + tid;
        int c = g_cls[p];
        int my_pre = 0;
        #pragma unroll
        for (int cc = 1; cc < NC; cc++) {
            unsigned bal = __ballot_sync(0xffffffffu, c == cc);
            if (c == cc) my_pre = __popc(bal & lmask);
            if (lane == 0) wcnt[cc][wid] = __popc(bal);
        }
        __syncthreads();
        if (wid < NC - 1) {
            int cc = wid + 1;
            int v = wcnt[cc][lane];
            int inc = v;
            #pragma unroll
            for (int o = 1; o < 32; o <<= 1) {
                int t2 = __shfl_up_sync(0xffffffffu, inc, o);
                if (lane >= o) inc += t2;
            }
            woff[cc][lane] = inc - v;
            if (lane == 31) wtot[cc] = inc;
        }
        __syncthreads();
        if (c > 0) {
            int pos = cstart[c] + running[c] + woff[c][wid] + my_pre;
            g_cidx[pos] = p;
            g_ccls[pos] = c;
        }
        __syncthreads();
        if (tid >= 1 && tid < NC) running[tid] += wtot[tid];
        __syncthreads();
    }

    // compaction copy: warp per row, padded to TILE multiple with zeros
    int nv = g_nvalid;
    int nvpad = (nv + TILE - 1) & ~(TILE - 1);
    for (int pos = wid; pos < nvpad; pos += 32) {
        if (pos < nv) {
            int src = g_cidx[pos];
            g_cf[pos * DIM + lane]      = g_fn[src * DIM + lane];
            g_cf[pos * DIM + 32 + lane] = g_fn[src * DIM + 32 + lane];
        } else {
            g_cf[pos * DIM + lane]      = 0.f;
            g_cf[pos * DIM + 32 + lane] = 0.f;
            if (lane == 0) g_ccls[pos] = 0;
        }
    }
}

// ---------------- K3: pairwise relu(dot), 4x4 register blocking ------------
__global__ void __launch_bounds__(256, 2) k3_pairs(float* __restrict__ out) {
    __shared__ float4 As[TILE][PITCHF4];
    __shared__ float4 Bs[TILE][PITCHF4];
    __shared__ int    acl[TILE], bcl[TILE];
    __shared__ float  scross[NC * NC];

    int tid = threadIdx.x;
    int tx = tid & 15, ty = tid >> 4;
    for (int i = tid; i < NC * NC; i += 256) scross[i] = 0.f;

    int nv = g_nvalid;
    int nt = (nv + TILE - 1) / TILE;
    int ntp = nt * (nt + 1) / 2;

    const float4* cf4 = (const float4*)g_cf;

    for (int k = blockIdx.x; k < ntp; k += gridDim.x) {
        int tj = (int)((sqrtf(8.0f * (float)k + 1.0f) - 1.0f) * 0.5f);
        while ((tj + 1) * (tj + 2) / 2 <= k) tj++;
        while (tj * (tj + 1) / 2 > k) tj--;
        int ti = k - tj * (tj + 1) / 2;

        __syncthreads();
        // coalesced tile loads from compacted features (no bounds checks)
        #pragma unroll
        for (int q0 = 0; q0 < TILE * NF4; q0 += 256) {
            int q = q0 + tid;
            int row = q >> 4, c4 = q & 15;
            As[row][c4] = cf4[(ti * TILE + row) * NF4 + c4];
            Bs[row][c4] = cf4[(tj * TILE + row) * NF4 + c4];
        }
        if (tid < TILE) {
            acl[tid] = g_ccls[ti * TILE + tid];
            bcl[tid] = g_ccls[tj * TILE + tid];
        }
        __syncthreads();

        // thread block: i rows 4ty..4ty+3 (contiguous), j rows tx+16s (strided)
        int i0 = ty * 4;
        int jr0 = tx, jr1 = tx + 16, jr2 = tx + 32, jr3 = tx + 48;
        int ca = acl[i0];
        int cb = bcl[jr0];
        bool ua = (acl[i0+1] == ca) & (acl[i0+2] == ca) & (acl[i0+3] == ca);
        bool ub = (bcl[jr1] == cb) & (bcl[jr2] == cb) & (bcl[jr3] == cb);
        bool diag = (ti == tj);

        bool uniform = ua && ub;
        if (uniform && (ca == cb || ca == 0 || cb == 0)) continue;

        float acc[16];
        #pragma unroll
        for (int r = 0; r < 16; r++) acc[r] = 0.f;
        #pragma unroll
        for (int dd = 0; dd < NF4; dd++) {
            float4 a0 = As[i0][dd],  a1 = As[i0+1][dd];
            float4 a2 = As[i0+2][dd], a3 = As[i0+3][dd];
            float4 b0 = Bs[jr0][dd], b1 = Bs[jr1][dd];
            float4 b2 = Bs[jr2][dd], b3 = Bs[jr3][dd];
            float4 ar[4] = {a0, a1, a2, a3};
            float4 br[4] = {b0, b1, b2, b3};
            #pragma unroll
            for (int r = 0; r < 4; r++)
                #pragma unroll
                for (int s = 0; s < 4; s++)
                    acc[r * 4 + s] += ar[r].x * br[s].x + ar[r].y * br[s].y
                                    + ar[r].z * br[s].z + ar[r].w * br[s].w;
        }

        if (uniform) {
            float s = 0.f;
            if (!diag) {
                #pragma unroll
                for (int r = 0; r < 16; r++) s += fmaxf(acc[r], 0.f);
            } else {
                // strict i<j on diagonal tiles
                #pragma unroll
                for (int r = 0; r < 4; r++) {
                    #pragma unroll
                    for (int sI = 0; sI < 4; sI++)
                        if (i0 + r < tx + 16 * sI) s += fmaxf(acc[r * 4 + sI], 0.f);
                }
            }
            if (s > 0.f) {
                int lo = min(ca, cb), hi = max(ca, cb);
                atomicAdd(&scross[lo * NC + hi], s);
            }
        } else {
            int jcl[4] = {bcl[jr0], bcl[jr1], bcl[jr2], bcl[jr3]};
            int jid[4] = {jr0, jr1, jr2, jr3};
            #pragma unroll
            for (int r = 0; r < 4; r++) {
                int ci = acl[i0 + r];
                #pragma unroll
                for (int sI = 0; sI < 4; sI++) {
                    int cj = jcl[sI];
                    if (ci == 0 || cj == 0 || ci == cj) continue;
                    if (diag && (i0 + r) >= jid[sI]) continue;
                    float v = acc[r * 4 + sI];
                    if (v > 0.f) {
                        int lo = min(ci, cj), hi = max(ci, cj);
                        atomicAdd(&scross[lo * NC + hi], v);
                    }
                }
            }
        }
    }
    __syncthreads();
    for (int i = tid; i < NC * NC; i += 256)
        if (scross[i] != 0.f) atomicAdd(&g_cross[i], scross[i]);

    // ---- last-block finalize ----
    __shared__ bool is_last;
    __threadfence();
    __syncthreads();
    if (tid == 0) is_last = (atomicAdd(&g_ticket, 1u) == gridDim.x - 1);
    __syncthreads();
    if (!is_last) return;
    __threadfence();

    __shared__ float red[256];
    float acc = 0.f;
    if (tid >= 1 && tid < NC) {
        float cnt = (float)g_cnt[tid];
        float quad = 0.f;
        #pragma unroll
        for (int d = 0; d < DIM; d++) {
            float v = g_sum[tid * DIM + d];
            quad += v * v;
        }
        float npairs = cnt * (cnt - 1.0f) * 0.5f;
        if (npairs > 0.f)
            acc += 1.0f - ((quad - cnt) * 0.5f) / npairs;
    }
    for (int idx = tid; idx < NC * NC; idx += 256) {
        int a = idx / NC, b = idx % NC;
        if (a >= 1 && b > a) {
            float den = (float)g_cnt[a] * (float)g_cnt[b];
            if (den > 0.f) acc += g_cross[a * NC + b] / den;
        }
    }
    red[tid] = acc;
    __syncthreads();
    #pragma unroll
    for (int o = 128; o > 0; o >>= 1) {
        if (tid < o) red[tid] += red[tid + o];
        __syncthreads();
    }
    if (tid == 0) out[0] = red[0];
}

extern "C" void kernel_launch(void* const* d_in, const int* in_sizes, int n_in,
                              void* d_out, int out_size) {
    const int*   labels = nullptr;
    const float* feats  = nullptr;
    const float* scores = nullptr;
    for (int i = 0; i < n_in; i++) {
        if (in_sizes[i] == NPTS)            labels = (const int*)d_in[i];
        else if (in_sizes[i] == NPTS * DIM) feats  = (const float*)d_in[i];
        else if (in_sizes[i] == NPTS * NC)  scores = (const float*)d_in[i];
    }
    float* out = (float*)d_out;

    k0_zero<<<1, 256>>>();
    k1_classify<<<(NPTS * 32) / 256, 256>>>(labels, feats, scores);
    k2_sort<<<1, 1024>>>();
    k3_pairs<<<NB3, 256>>>(out);
}

// round 5
// speedup vs baseline: 1.3009x; 1.3009x over previous
#include <cuda_runtime.h>
#include <math.h>

#define NPTS 16384
#define DIM  64
#define NC   9
#define TILE 32
#define NF4  16      // float4s per feature row
#define PITCHF4 17   // smem tile pitch in float4
#define NB3  592     // k3 grid (4 per SM)

// ---- device scratch (zero-initialized at module load; k3 re-zeros per run) ----
__device__ float g_fn[NPTS * DIM];       // normalized features (valid points only)
__device__ float g_cf[NPTS * DIM];       // compacted class-sorted features (padded)
__device__ int   g_cls[NPTS];            // class 1..8 if valid member, else 0
__device__ int   g_cidx[NPTS];           // class-sorted point indices
__device__ int   g_ccls[NPTS + TILE];    // class-sorted classes (padded with 0)
__device__ int   g_nvalid;
__device__ int   g_cnt[NC];
__device__ float g_sum[NC * DIM];        // per-class normalized-feature sums
__device__ float g_cross[NC * NC];       // relu(dot) sums per unordered class pair
__device__ unsigned g_ticket;

// ---------------- K1: classify + normalize (1 warp / point) ----------------
__global__ void k1_classify(const int* __restrict__ labels,
                            const float* __restrict__ feats,
                            const float* __restrict__ scores) {
    int warp = (blockIdx.x * blockDim.x + threadIdx.x) >> 5;
    int lane = threadIdx.x & 31;
    if (warp >= NPTS) return;
    int p = warp;

    float x0 = feats[p * DIM + lane];
    float x1 = feats[p * DIM + 32 + lane];
    float ss = x0 * x0 + x1 * x1;
    #pragma unroll
    for (int o = 16; o > 0; o >>= 1) ss += __shfl_xor_sync(0xffffffffu, ss, o);
    float inv = 1.0f / fmaxf(sqrtf(ss), 1e-12f);

    float s = (lane < NC) ? scores[p * NC + lane] : -INFINITY;
    float mval = s; int midx = lane;
    #pragma unroll
    for (int o = 16; o > 0; o >>= 1) {
        float ov = __shfl_xor_sync(0xffffffffu, mval, o);
        int   oi = __shfl_xor_sync(0xffffffffu, midx, o);
        if (ov > mval || (ov == mval && oi < midx)) { mval = ov; midx = oi; }
    }
    float e = (lane < NC) ? expf(s - mval) : 0.f;
    #pragma unroll
    for (int o = 16; o > 0; o >>= 1) e += __shfl_xor_sync(0xffffffffu, e, o);
    float pmax = 1.0f / e;

    int lab = labels[p];
    int valid = (lab == midx) && (pmax >= 0.5f);
    int cls = (valid && lab >= 1) ? lab : 0;

    if (lane == 0) g_cls[p] = cls;
    if (cls > 0) {
        float f0 = x0 * inv, f1 = x1 * inv;
        g_fn[p * DIM + lane]      = f0;
        g_fn[p * DIM + 32 + lane] = f1;
        atomicAdd(&g_sum[cls * DIM + lane],      f0);
        atomicAdd(&g_sum[cls * DIM + 32 + lane], f1);
        if (lane == 0) atomicAdd(&g_cnt[cls], 1);
    }
}

// ------- K2: class-stable counting sort + compaction copy (1 block) --------
__global__ void k2_sort() {
    __shared__ int cstart[NC];
    __shared__ int running[NC];
    __shared__ int wcnt[NC][32];
    __shared__ int woff[NC][32];
    __shared__ int wtot[NC];
    int tid = threadIdx.x, lane = tid & 31, wid = tid >> 5;

    if (tid == 0) {
        int acc = 0;
        for (int c = 1; c < NC; c++) { cstart[c] = acc; acc += g_cnt[c]; }
        g_nvalid = acc;
    }
    if (tid < NC) running[tid] = 0;
    __syncthreads();

    unsigned lmask = (1u << lane) - 1u;
    for (int start = 0; start < NPTS; start += 1024) {
        int p = start + tid;
        int c = g_cls[p];
        int my_pre = 0;
        #pragma unroll
        for (int cc = 1; cc < NC; cc++) {
            unsigned bal = __ballot_sync(0xffffffffu, c == cc);
            if (c == cc) my_pre = __popc(bal & lmask);
            if (lane == 0) wcnt[cc][wid] = __popc(bal);
        }
        __syncthreads();
        if (wid < NC - 1) {
            int cc = wid + 1;
            int v = wcnt[cc][lane];
            int inc = v;
            #pragma unroll
            for (int o = 1; o < 32; o <<= 1) {
                int t2 = __shfl_up_sync(0xffffffffu, inc, o);
                if (lane >= o) inc += t2;
            }
            woff[cc][lane] = inc - v;
            if (lane == 31) wtot[cc] = inc;
        }
        __syncthreads();
        if (c > 0) {
            int pos = cstart[c] + running[c] + woff[c][wid] + my_pre;
            g_cidx[pos] = p;
            g_ccls[pos] = c;
        }
        __syncthreads();
        if (tid >= 1 && tid < NC) running[tid] += wtot[tid];
        __syncthreads();
    }

    // compaction copy: warp per row, padded to TILE multiple with zeros
    int nv = g_nvalid;
    int nvpad = (nv + TILE - 1) & ~(TILE - 1);
    for (int pos = wid; pos < nvpad; pos += 32) {
        if (pos < nv) {
            int src = g_cidx[pos];
            g_cf[pos * DIM + lane]      = g_fn[src * DIM + lane];
            g_cf[pos * DIM + 32 + lane] = g_fn[src * DIM + 32 + lane];
        } else {
            g_cf[pos * DIM + lane]      = 0.f;
            g_cf[pos * DIM + 32 + lane] = 0.f;
            if (lane == 0) g_ccls[pos] = 0;
        }
    }
}

// ------ K3: pairwise relu(dot), 32x32 tiles, 4x2 register blocking --------
__global__ void __launch_bounds__(128, 8) k3_pairs(float* __restrict__ out) {
    __shared__ float4 As[TILE][PITCHF4];
    __shared__ float4 Bs[TILE][PITCHF4];
    __shared__ int    acl[TILE], bcl[TILE];
    __shared__ float  scross[NC * NC];

    int tid = threadIdx.x;
    int tx = tid & 15, ty = tid >> 4;          // tx 0..15, ty 0..7
    for (int i = tid; i < NC * NC; i += 128) scross[i] = 0.f;

    int nv = g_nvalid;
    int nt = (nv + TILE - 1) / TILE;
    int ntp = nt * (nt + 1) / 2;

    const float4* cf4 = (const float4*)g_cf;

    for (int k = blockIdx.x; k < ntp; k += NB3) {
        int tj = (int)((sqrtf(8.0f * (float)k + 1.0f) - 1.0f) * 0.5f);
        while ((tj + 1) * (tj + 2) / 2 <= k) tj++;
        while (tj * (tj + 1) / 2 > k) tj--;
        int ti = k - tj * (tj + 1) / 2;

        __syncthreads();
        // coalesced tile loads: 512 float4 per tile, 128 threads -> 4 each
        #pragma unroll
        for (int q0 = 0; q0 < TILE * NF4; q0 += 128) {
            int q = q0 + tid;
            int row = q >> 4, c4 = q & 15;
            As[row][c4] = cf4[(ti * TILE + row) * NF4 + c4];
            Bs[row][c4] = cf4[(tj * TILE + row) * NF4 + c4];
        }
        if (tid < TILE) {
            acl[tid] = g_ccls[ti * TILE + tid];
            bcl[tid] = g_ccls[tj * TILE + tid];
        }
        __syncthreads();

        // thread micro-tile: i rows 4ty..4ty+3, j rows {tx, tx+16}
        int i0 = ty * 4;
        int jr0 = tx, jr1 = tx + 16;
        int ca = acl[i0];
        int cb = bcl[jr0];
        bool ua = (acl[i0+1] == ca) & (acl[i0+2] == ca) & (acl[i0+3] == ca);
        bool ub = (bcl[jr1] == cb);
        bool diag = (ti == tj);
        bool uniform = ua && ub;
        if (uniform && (ca == cb || ca == 0 || cb == 0)) continue;

        float acc[8];
        #pragma unroll
        for (int r = 0; r < 8; r++) acc[r] = 0.f;
        #pragma unroll
        for (int dd = 0; dd < NF4; dd++) {
            float4 ar[4] = { As[i0][dd], As[i0+1][dd], As[i0+2][dd], As[i0+3][dd] };
            float4 br[2] = { Bs[jr0][dd], Bs[jr1][dd] };
            #pragma unroll
            for (int r = 0; r < 4; r++)
                #pragma unroll
                for (int s = 0; s < 2; s++)
                    acc[r * 2 + s] += ar[r].x * br[s].x + ar[r].y * br[s].y
                                    + ar[r].z * br[s].z + ar[r].w * br[s].w;
        }

        if (uniform) {
            float s = 0.f;
            if (!diag) {
                #pragma unroll
                for (int r = 0; r < 8; r++) s += fmaxf(acc[r], 0.f);
            } else {
                #pragma unroll
                for (int r = 0; r < 4; r++) {
                    if (i0 + r < jr0) s += fmaxf(acc[r * 2 + 0], 0.f);
                    if (i0 + r < jr1) s += fmaxf(acc[r * 2 + 1], 0.f);
                }
            }
            if (s > 0.f) {
                int lo = min(ca, cb), hi = max(ca, cb);
                atomicAdd(&scross[lo * NC + hi], s);
            }
        } else {
            int jcl[2] = { bcl[jr0], bcl[jr1] };
            int jid[2] = { jr0, jr1 };
            #pragma unroll
            for (int r = 0; r < 4; r++) {
                int ci = acl[i0 + r];
                #pragma unroll
                for (int s = 0; s < 2; s++) {
                    int cj = jcl[s];
                    if (ci == 0 || cj == 0 || ci == cj) continue;
                    if (diag && (i0 + r) >= jid[s]) continue;
                    float v = acc[r * 2 + s];
                    if (v > 0.f) {
                        int lo = min(ci, cj), hi = max(ci, cj);
                        atomicAdd(&scross[lo * NC + hi], v);
                    }
                }
            }
        }
    }
    __syncthreads();
    for (int i = tid; i < NC * NC; i += 128)
        if (scross[i] != 0.f) atomicAdd(&g_cross[i], scross[i]);

    // ---- last-block finalize + re-zero for next graph replay ----
    __shared__ bool is_last;
    __threadfence();
    __syncthreads();
    if (tid == 0) is_last = (atomicAdd(&g_ticket, 1u) == NB3 - 1);
    __syncthreads();
    if (!is_last) return;
    __threadfence();

    __shared__ float red[128];
    float acc = 0.f;
    if (tid >= 1 && tid < NC) {
        float cnt = (float)g_cnt[tid];
        float quad = 0.f;
        #pragma unroll
        for (int d = 0; d < DIM; d++) {
            float v = g_sum[tid * DIM + d];
            quad += v * v;
        }
        float npairs = cnt * (cnt - 1.0f) * 0.5f;
        if (npairs > 0.f)
            acc += 1.0f - ((quad - cnt) * 0.5f) / npairs;
    }
    for (int idx = tid; idx < NC * NC; idx += 128) {
        int a = idx / NC, b = idx % NC;
        if (a >= 1 && b > a) {
            float den = (float)g_cnt[a] * (float)g_cnt[b];
            if (den > 0.f) acc += g_cross[a * NC + b] / den;
        }
    }
    red[tid] = acc;
    __syncthreads();
    #pragma unroll
    for (int o = 64; o > 0; o >>= 1) {
        if (tid < o) red[tid] += red[tid + o];
        __syncthreads();
    }
    if (tid == 0) out[0] = red[0];

    // re-zero accumulators so the next replay starts clean
    __syncthreads();
    if (tid < NC) g_cnt[tid] = 0;
    if (tid < NC * NC) g_cross[tid] = 0.f;
    for (int i = tid; i < NC * DIM; i += 128) g_sum[i] = 0.f;
    if (tid == 0) { g_nvalid = 0; g_ticket = 0; }
}

extern "C" void kernel_launch(void* const* d_in, const int* in_sizes, int n_in,
                              void* d_out, int out_size) {
    const int*   labels = nullptr;
    const float* feats  = nullptr;
    const float* scores = nullptr;
    for (int i = 0; i < n_in; i++) {
        if (in_sizes[i] == NPTS)            labels = (const int*)d_in[i];
        else if (in_sizes[i] == NPTS * DIM) feats  = (const float*)d_in[i];
        else if (in_sizes[i] == NPTS * NC)  scores = (const float*)d_in[i];
    }
    float* out = (float*)d_out;

    k1_classify<<<(NPTS * 32) / 256, 256>>>(labels, feats, scores);
    k2_sort<<<1, 1024>>>();
    k3_pairs<<<NB3, 128>>>(out);
}